// round 7
// baseline (speedup 1.0000x reference)
#include <cuda_runtime.h>
#include <cuda_fp16.h>
#include <cstdint>

// ---------------- Problem constants ----------------
static constexpr int MDIM = 8192;
static constexpr int NDIM = 8192;
static constexpr int KDIM = 2048;

static constexpr int TILE_M = 128;
static constexpr int TILE_N = 256;
static constexpr int BK     = 64;            // 128B rows in smem (fp16)
static constexpr int STAGES = 4;             // ring slots (3 in flight + WAR slack)
static constexpr int NITER  = KDIM / BK;     // 32

static constexpr int MT_TILES = MDIM / TILE_M;   // 64
static constexpr int NT_TILES = NDIM / TILE_N;   // 32

static constexpr int A_BYTES     = TILE_M * 128;             // 16384
static constexpr int B_BYTES     = TILE_N * 128;             // 32768
static constexpr int STAGE_BYTES = A_BYTES + B_BYTES;        // 49152
static constexpr int SMEM_TOTAL  = STAGES * STAGE_BYTES;     // 196608

// Static device scratch (no runtime allocation)
__device__ __half g_X[(size_t)MDIM * KDIM];   // 33.5 MB
__device__ __half g_W[(size_t)NDIM * KDIM];   // 33.5 MB

// ---------------- Helpers ----------------
__device__ __forceinline__ uint32_t smem_u32(const void* p) {
    uint32_t a;
    asm("{ .reg .u64 t; cvta.to.shared.u64 t, %1; cvt.u32.u64 %0, t; }" : "=r"(a) : "l"(p));
    return a;
}
__device__ __forceinline__ void cp_async16(uint32_t dst, const void* src) {
    asm volatile("cp.async.cg.shared.global [%0], [%1], 16;" :: "r"(dst), "l"(src));
}
__device__ __forceinline__ void cp_commit() {
    asm volatile("cp.async.commit_group;" ::: "memory");
}
__device__ __forceinline__ void cp_wait2() {
    asm volatile("cp.async.wait_group 2;" ::: "memory");
}
__device__ __forceinline__ void ldsm_x4(uint32_t& r0, uint32_t& r1, uint32_t& r2, uint32_t& r3,
                                        uint32_t addr) {
    asm volatile("ldmatrix.sync.aligned.m8n8.x4.shared.b16 {%0,%1,%2,%3}, [%4];"
                 : "=r"(r0), "=r"(r1), "=r"(r2), "=r"(r3) : "r"(addr));
}
__device__ __forceinline__ void mma16816(float& d0, float& d1, float& d2, float& d3,
                                         uint32_t a0, uint32_t a1, uint32_t a2, uint32_t a3,
                                         uint32_t b0, uint32_t b1) {
    asm volatile("mma.sync.aligned.m16n8k16.row.col.f32.f16.f16.f32 "
                 "{%0,%1,%2,%3}, {%4,%5,%6,%7}, {%8,%9}, {%0,%1,%2,%3};"
                 : "+f"(d0), "+f"(d1), "+f"(d2), "+f"(d3)
                 : "r"(a0), "r"(a1), "r"(a2), "r"(a3), "r"(b0), "r"(b1));
}
#define SWZ128(o) ((o) ^ (((o) >> 3) & 0x70))

// ---------------- Fused prep kernel (convert x + dequant W, one launch) ----------------
static constexpr int CONV_BLOCKS = 16384;   // 8192*2048/4 float4 / 256 threads
static constexpr int DEQ_BLOCKS  = 32768;   // 8192*1024 packed / 256 threads

__global__ void __launch_bounds__(256) prep_kernel(const float* __restrict__ x,
                                                   const int* __restrict__ packed,
                                                   const float* __restrict__ scales,
                                                   const int* __restrict__ zeros) {
    if (blockIdx.x < CONV_BLOCKS) {
        size_t i = (size_t)blockIdx.x * 256 + threadIdx.x;    // one float4 each
        float4 v = reinterpret_cast<const float4*>(x)[i];
        __half2* dst = reinterpret_cast<__half2*>(g_X);
        dst[2 * i]     = __floats2half2_rn(v.x, v.y);
        dst[2 * i + 1] = __floats2half2_rn(v.z, v.w);
    } else {
        size_t i = (size_t)(blockIdx.x - CONV_BLOCKS) * 256 + threadIdx.x;
        int p = packed[i];
        int n = (int)(i >> 10);
        int j = (int)(i & 1023);
        int g = j >> 5;                     // 32 packed per group (64 k per group)
        float s = scales[n * 32 + g];
        float z = (float)zeros[n * 32 + g];
        float lo = ((float)(p & 15) - z) * s;
        float hi = ((float)((p >> 4) & 15) - z) * s;
        *reinterpret_cast<__half2*>(g_W + (size_t)n * KDIM + 2 * j) = __floats2half2_rn(lo, hi);
    }
}

// ---------------- GEMM kernel (mma.sync HMMA, cp.async multistage) ----------------
__global__ void __launch_bounds__(256, 1) gemm_kernel(float* __restrict__ out,
                                                      const float* __restrict__ bias) {
    extern __shared__ char smem[];
    const uint32_t sb = smem_u32(smem);
    const int tid  = threadIdx.x;
    const int wid  = tid >> 5;
    const int lane = tid & 31;

    // Supertiled ordering: groups of 16 M-tiles sweep all 32 N-tiles (L2 reuse of W)
    const int SUPER = 16;
    int bid = blockIdx.x;
    int per_super = SUPER * NT_TILES;             // 512
    int sid = bid / per_super;
    int rem = bid % per_super;
    int mt  = sid * SUPER + (rem % SUPER);
    int nt  = rem / SUPER;
    const int m_base = mt * TILE_M;
    const int n_base = nt * TILE_N;

    // Warp tiling: 2 (M) x 4 (N) warps, each computes 64x64
    const int warp_m = wid & 1;
    const int warp_n = wid >> 1;

    const __half* gx = g_X + (size_t)m_base * KDIM;   // A tile rows
    const __half* gw = g_W + (size_t)n_base * KDIM;   // B tile rows

    // ---- producer: issue one stage of cp.async (12 x 16B per thread) ----
    auto issue_stage = [&](int j) {
        uint32_t base = sb + (j & (STAGES - 1)) * STAGE_BYTES;
        int k0 = j * BK;
        #pragma unroll
        for (int i = 0; i < 4; i++) {               // A: 1024 chunks
            int c = tid + 256 * i;
            int r = c >> 3, cc = c & 7;
            cp_async16(base + SWZ128(r * 128 + cc * 16),
                       gx + (size_t)r * KDIM + k0 + cc * 8);
        }
        #pragma unroll
        for (int i = 0; i < 8; i++) {               // B: 2048 chunks
            int c = tid + 256 * i;
            int r = c >> 3, cc = c & 7;
            cp_async16(base + A_BYTES + SWZ128(r * 128 + cc * 16),
                       gw + (size_t)r * KDIM + k0 + cc * 8);
        }
    };

    // Per-lane ldmatrix base offsets (unswizzled) + swizzle masks
    const int rowA  = warp_m * 64 + (lane & 15);
    const uint32_t offA  = (uint32_t)rowA * 128 + ((lane >> 4) << 4);
    const uint32_t maskA = (uint32_t)(rowA & 7) << 4;
    const int rowB  = warp_n * 64 + (lane & 7) + ((lane >> 4) << 3);
    const uint32_t offB  = (uint32_t)rowB * 128 + (((lane >> 3) & 1) << 4);
    const uint32_t maskB = (uint32_t)(rowB & 7) << 4;

    float d[4][8][4];
    #pragma unroll
    for (int m = 0; m < 4; m++)
        #pragma unroll
        for (int n = 0; n < 8; n++)
            #pragma unroll
            for (int e = 0; e < 4; e++) d[m][n][e] = 0.0f;

    // Double-buffered fragments (k-level software pipeline)
    uint32_t a[2][4][4];
    uint32_t b[2][8][2];

    // Prologue: fill 3 stages (depth-3 pipeline, 4th slot = WAR slack)
    issue_stage(0); cp_commit();
    issue_stage(1); cp_commit();
    issue_stage(2); cp_commit();

    for (int j = 0; j < NITER; j++) {
        cp_wait2();          // own copies of stage j done (all but last 2 groups)
        __syncthreads();     // all threads' stage-j copies visible; orders slot reuse

        if (j + 3 < NITER) issue_stage(j + 3);
        cp_commit();         // empty groups at tail keep group accounting uniform

        uint32_t sA = sb + (j & (STAGES - 1)) * STAGE_BYTES;
        uint32_t sB = sA + A_BYTES;

        // Load k=0 fragments into buffer 0
        #pragma unroll
        for (int m = 0; m < 4; m++) {
            uint32_t off = offA + (uint32_t)m * 2048;
            ldsm_x4(a[0][m][0], a[0][m][1], a[0][m][2], a[0][m][3], sA + (off ^ maskA));
        }
        #pragma unroll
        for (int nf = 0; nf < 4; nf++) {
            uint32_t off = offB + (uint32_t)nf * 2048;
            ldsm_x4(b[0][2 * nf][0], b[0][2 * nf][1], b[0][2 * nf + 1][0], b[0][2 * nf + 1][1],
                    sB + (off ^ maskB));
        }

        #pragma unroll
        for (int k = 0; k < 4; k++) {                // 4 x k16 per stage
            const int cur = k & 1, nxt = cur ^ 1;
            if (k < 3) {
                // Prefetch k+1 fragments; ptxas interleaves these LDSMs among the HMMAs below
                #pragma unroll
                for (int m = 0; m < 4; m++) {
                    uint32_t off = offA + (uint32_t)m * 2048 + (uint32_t)(k + 1) * 32;
                    ldsm_x4(a[nxt][m][0], a[nxt][m][1], a[nxt][m][2], a[nxt][m][3],
                            sA + (off ^ maskA));
                }
                #pragma unroll
                for (int nf = 0; nf < 4; nf++) {
                    uint32_t off = offB + (uint32_t)nf * 2048 + (uint32_t)(k + 1) * 32;
                    ldsm_x4(b[nxt][2 * nf][0], b[nxt][2 * nf][1],
                            b[nxt][2 * nf + 1][0], b[nxt][2 * nf + 1][1],
                            sB + (off ^ maskB));
                }
            }
            #pragma unroll
            for (int m = 0; m < 4; m++)
                #pragma unroll
                for (int n = 0; n < 8; n++)
                    mma16816(d[m][n][0], d[m][n][1], d[m][n][2], d[m][n][3],
                             a[cur][m][0], a[cur][m][1], a[cur][m][2], a[cur][m][3],
                             b[cur][n][0], b[cur][n][1]);
        }
        // no trailing barrier: next iteration's leading barrier orders slot reuse
    }

    // ---- epilogue: bias add + store ----
    float2 bb[8];
    #pragma unroll
    for (int n = 0; n < 8; n++) {
        int col = n_base + warp_n * 64 + n * 8 + 2 * (lane & 3);
        bb[n] = *reinterpret_cast<const float2*>(bias + col);
    }
    #pragma unroll
    for (int m = 0; m < 4; m++) {
        int r0 = m_base + warp_m * 64 + m * 16 + (lane >> 2);
        float* p0 = out + (size_t)r0 * NDIM;
        float* p1 = p0 + (size_t)8 * NDIM;
        #pragma unroll
        for (int n = 0; n < 8; n++) {
            int col = n_base + warp_n * 64 + n * 8 + 2 * (lane & 3);
            float2 v0 = make_float2(d[m][n][0] + bb[n].x, d[m][n][1] + bb[n].y);
            float2 v1 = make_float2(d[m][n][2] + bb[n].x, d[m][n][3] + bb[n].y);
            *reinterpret_cast<float2*>(p0 + col) = v0;
            *reinterpret_cast<float2*>(p1 + col) = v1;
        }
    }
}

// ---------------- Launch ----------------
extern "C" void kernel_launch(void* const* d_in, const int* in_sizes, int n_in,
                              void* d_out, int out_size) {
    const float* x      = (const float*)d_in[0];
    const int*   packed = (const int*)d_in[1];
    const float* scales = (const float*)d_in[2];
    const int*   zeros  = (const int*)d_in[3];
    const float* bias   = (const float*)d_in[4];
    float* out = (float*)d_out;

    cudaFuncSetAttribute(gemm_kernel, cudaFuncAttributeMaxDynamicSharedMemorySize, SMEM_TOTAL);

    prep_kernel<<<CONV_BLOCKS + DEQ_BLOCKS, 256>>>(x, packed, scales, zeros);
    gemm_kernel<<<MT_TILES * NT_TILES, 256, SMEM_TOTAL>>>(out, bias);
}

// round 8
// speedup vs baseline: 1.0102x; 1.0102x over previous
#include <cuda_runtime.h>
#include <cuda_fp16.h>
#include <cstdint>

// ---------------- Problem constants ----------------
static constexpr int MDIM = 8192;
static constexpr int NDIM = 8192;
static constexpr int KDIM = 2048;

static constexpr int TILE_M = 128;
static constexpr int TILE_N = 256;
static constexpr int BK     = 64;            // 128B rows in smem (fp16)
static constexpr int STAGES = 4;             // ring slots (3 in flight + WAR slack)
static constexpr int NITER  = KDIM / BK;     // 32
static constexpr int NTHREADS = 512;         // 16 warps: 2(M) x 8(N), warp tile 64x32

static constexpr int MT_TILES = MDIM / TILE_M;   // 64
static constexpr int NT_TILES = NDIM / TILE_N;   // 32

static constexpr int A_BYTES     = TILE_M * 128;             // 16384
static constexpr int B_BYTES     = TILE_N * 128;             // 32768
static constexpr int STAGE_BYTES = A_BYTES + B_BYTES;        // 49152
static constexpr int SMEM_TOTAL  = STAGES * STAGE_BYTES;     // 196608

// Static device scratch (no runtime allocation)
__device__ __half g_X[(size_t)MDIM * KDIM];   // 33.5 MB
__device__ __half g_W[(size_t)NDIM * KDIM];   // 33.5 MB

// ---------------- Helpers ----------------
__device__ __forceinline__ uint32_t smem_u32(const void* p) {
    uint32_t a;
    asm("{ .reg .u64 t; cvta.to.shared.u64 t, %1; cvt.u32.u64 %0, t; }" : "=r"(a) : "l"(p));
    return a;
}
__device__ __forceinline__ void cp_async16(uint32_t dst, const void* src) {
    asm volatile("cp.async.cg.shared.global [%0], [%1], 16;" :: "r"(dst), "l"(src));
}
__device__ __forceinline__ void cp_commit() {
    asm volatile("cp.async.commit_group;" ::: "memory");
}
__device__ __forceinline__ void cp_wait2() {
    asm volatile("cp.async.wait_group 2;" ::: "memory");
}
__device__ __forceinline__ void ldsm_x4(uint32_t& r0, uint32_t& r1, uint32_t& r2, uint32_t& r3,
                                        uint32_t addr) {
    asm volatile("ldmatrix.sync.aligned.m8n8.x4.shared.b16 {%0,%1,%2,%3}, [%4];"
                 : "=r"(r0), "=r"(r1), "=r"(r2), "=r"(r3) : "r"(addr));
}
__device__ __forceinline__ void mma16816(float& d0, float& d1, float& d2, float& d3,
                                         uint32_t a0, uint32_t a1, uint32_t a2, uint32_t a3,
                                         uint32_t b0, uint32_t b1) {
    asm volatile("mma.sync.aligned.m16n8k16.row.col.f32.f16.f16.f32 "
                 "{%0,%1,%2,%3}, {%4,%5,%6,%7}, {%8,%9}, {%0,%1,%2,%3};"
                 : "+f"(d0), "+f"(d1), "+f"(d2), "+f"(d3)
                 : "r"(a0), "r"(a1), "r"(a2), "r"(a3), "r"(b0), "r"(b1));
}
#define SWZ128(o) ((o) ^ (((o) >> 3) & 0x70))

// ---------------- Fused prep kernel (convert x + dequant W, one launch) ----------------
static constexpr int CONV_BLOCKS = 16384;   // 8192*2048/4 float4 / 256 threads
static constexpr int DEQ_BLOCKS  = 32768;   // 8192*1024 packed / 256 threads

__global__ void __launch_bounds__(256) prep_kernel(const float* __restrict__ x,
                                                   const int* __restrict__ packed,
                                                   const float* __restrict__ scales,
                                                   const int* __restrict__ zeros) {
    if (blockIdx.x < CONV_BLOCKS) {
        size_t i = (size_t)blockIdx.x * 256 + threadIdx.x;    // one float4 each
        float4 v = reinterpret_cast<const float4*>(x)[i];
        __half2* dst = reinterpret_cast<__half2*>(g_X);
        dst[2 * i]     = __floats2half2_rn(v.x, v.y);
        dst[2 * i + 1] = __floats2half2_rn(v.z, v.w);
    } else {
        size_t i = (size_t)(blockIdx.x - CONV_BLOCKS) * 256 + threadIdx.x;
        int p = packed[i];
        int n = (int)(i >> 10);
        int j = (int)(i & 1023);
        int g = j >> 5;                     // 32 packed per group (64 k per group)
        float s = scales[n * 32 + g];
        float z = (float)zeros[n * 32 + g];
        float lo = ((float)(p & 15) - z) * s;
        float hi = ((float)((p >> 4) & 15) - z) * s;
        *reinterpret_cast<__half2*>(g_W + (size_t)n * KDIM + 2 * j) = __floats2half2_rn(lo, hi);
    }
}

// ---------------- GEMM kernel (mma.sync HMMA, cp.async multistage, 16 warps) ----------------
__global__ void __launch_bounds__(NTHREADS, 1) gemm_kernel(float* __restrict__ out,
                                                           const float* __restrict__ bias) {
    extern __shared__ char smem[];
    const uint32_t sb = smem_u32(smem);
    const int tid  = threadIdx.x;
    const int wid  = tid >> 5;
    const int lane = tid & 31;

    // Supertiled ordering: groups of 16 M-tiles sweep all 32 N-tiles (L2 reuse of W)
    const int SUPER = 16;
    int bid = blockIdx.x;
    int per_super = SUPER * NT_TILES;             // 512
    int sid = bid / per_super;
    int rem = bid % per_super;
    int mt  = sid * SUPER + (rem % SUPER);
    int nt  = rem / SUPER;
    const int m_base = mt * TILE_M;
    const int n_base = nt * TILE_N;

    // Warp tiling: 2 (M) x 8 (N) warps, each computes 64x32
    const int warp_m = wid & 1;
    const int warp_n = wid >> 1;

    const __half* gx = g_X + (size_t)m_base * KDIM;   // A tile rows
    const __half* gw = g_W + (size_t)n_base * KDIM;   // B tile rows

    // ---- producer: issue one stage of cp.async (6 x 16B per thread) ----
    auto issue_stage = [&](int j) {
        uint32_t base = sb + (j & (STAGES - 1)) * STAGE_BYTES;
        int k0 = j * BK;
        #pragma unroll
        for (int i = 0; i < 2; i++) {               // A: 1024 chunks
            int c = tid + NTHREADS * i;
            int r = c >> 3, cc = c & 7;
            cp_async16(base + SWZ128(r * 128 + cc * 16),
                       gx + (size_t)r * KDIM + k0 + cc * 8);
        }
        #pragma unroll
        for (int i = 0; i < 4; i++) {               // B: 2048 chunks
            int c = tid + NTHREADS * i;
            int r = c >> 3, cc = c & 7;
            cp_async16(base + A_BYTES + SWZ128(r * 128 + cc * 16),
                       gw + (size_t)r * KDIM + k0 + cc * 8);
        }
    };

    // Per-lane ldmatrix base offsets (unswizzled) + swizzle masks
    const int rowA  = warp_m * 64 + (lane & 15);
    const uint32_t offA  = (uint32_t)rowA * 128 + ((lane >> 4) << 4);
    const uint32_t maskA = (uint32_t)(rowA & 7) << 4;
    const int rowB  = warp_n * 32 + (lane & 7) + ((lane >> 4) << 3);
    const uint32_t offB  = (uint32_t)rowB * 128 + (((lane >> 3) & 1) << 4);
    const uint32_t maskB = (uint32_t)(rowB & 7) << 4;

    float d[4][4][4];
    #pragma unroll
    for (int m = 0; m < 4; m++)
        #pragma unroll
        for (int n = 0; n < 4; n++)
            #pragma unroll
            for (int e = 0; e < 4; e++) d[m][n][e] = 0.0f;

    // Prologue: fill 3 stages (depth-3 pipeline, 4th slot = WAR slack)
    issue_stage(0); cp_commit();
    issue_stage(1); cp_commit();
    issue_stage(2); cp_commit();

    for (int j = 0; j < NITER; j++) {
        cp_wait2();          // own copies of stage j done (all but last 2 groups)
        __syncthreads();     // all threads' stage-j copies visible; orders slot reuse

        if (j + 3 < NITER) issue_stage(j + 3);
        cp_commit();         // empty groups at tail keep group accounting uniform

        uint32_t sA = sb + (j & (STAGES - 1)) * STAGE_BYTES;
        uint32_t sB = sA + A_BYTES;

        #pragma unroll
        for (int k = 0; k < 4; k++) {                // 4 x k16 per stage
            uint32_t a[4][4];
            uint32_t b[4][2];
            #pragma unroll
            for (int m = 0; m < 4; m++) {
                uint32_t off = offA + (uint32_t)m * 2048 + (uint32_t)k * 32;
                ldsm_x4(a[m][0], a[m][1], a[m][2], a[m][3], sA + (off ^ maskA));
            }
            #pragma unroll
            for (int nf = 0; nf < 2; nf++) {
                uint32_t off = offB + (uint32_t)nf * 2048 + (uint32_t)k * 32;
                ldsm_x4(b[2 * nf][0], b[2 * nf][1], b[2 * nf + 1][0], b[2 * nf + 1][1],
                        sB + (off ^ maskB));
            }
            #pragma unroll
            for (int m = 0; m < 4; m++)
                #pragma unroll
                for (int n = 0; n < 4; n++)
                    mma16816(d[m][n][0], d[m][n][1], d[m][n][2], d[m][n][3],
                             a[m][0], a[m][1], a[m][2], a[m][3],
                             b[n][0], b[n][1]);
        }
        // no trailing barrier: next iteration's leading barrier orders slot reuse
    }

    // ---- epilogue: bias add + store ----
    float2 bb[4];
    #pragma unroll
    for (int n = 0; n < 4; n++) {
        int col = n_base + warp_n * 32 + n * 8 + 2 * (lane & 3);
        bb[n] = *reinterpret_cast<const float2*>(bias + col);
    }
    #pragma unroll
    for (int m = 0; m < 4; m++) {
        int r0 = m_base + warp_m * 64 + m * 16 + (lane >> 2);
        float* p0 = out + (size_t)r0 * NDIM;
        float* p1 = p0 + (size_t)8 * NDIM;
        #pragma unroll
        for (int n = 0; n < 4; n++) {
            int col = n_base + warp_n * 32 + n * 8 + 2 * (lane & 3);
            float2 v0 = make_float2(d[m][n][0] + bb[n].x, d[m][n][1] + bb[n].y);
            float2 v1 = make_float2(d[m][n][2] + bb[n].x, d[m][n][3] + bb[n].y);
            *reinterpret_cast<float2*>(p0 + col) = v0;
            *reinterpret_cast<float2*>(p1 + col) = v1;
        }
    }
}

// ---------------- Launch ----------------
extern "C" void kernel_launch(void* const* d_in, const int* in_sizes, int n_in,
                              void* d_out, int out_size) {
    const float* x      = (const float*)d_in[0];
    const int*   packed = (const int*)d_in[1];
    const float* scales = (const float*)d_in[2];
    const int*   zeros  = (const int*)d_in[3];
    const float* bias   = (const float*)d_in[4];
    float* out = (float*)d_out;

    cudaFuncSetAttribute(gemm_kernel, cudaFuncAttributeMaxDynamicSharedMemorySize, SMEM_TOTAL);

    prep_kernel<<<CONV_BLOCKS + DEQ_BLOCKS, 256>>>(x, packed, scales, zeros);
    gemm_kernel<<<MT_TILES * NT_TILES, NTHREADS, SMEM_TOTAL>>>(out, bias);
}